// round 14
// baseline (speedup 1.0000x reference)
#include <cuda_runtime.h>

// L1Distance via min identity, cross-pipe de-serialized:
//   out[i][j] = max(rsA[i] + rsB[j] - 2 * sum_d min(x1[i,d], x2[j,d]), 0)
// Inner loop computes 16 FMNMX into an explicit temp array, THEN 16 FADDs:
// every FADD sits >=16 slots after its producing FMNMX (cross-pipe RAW = 5cyc),
// so the alu and fma pipes stream concurrently at rt2 instead of serializing.

constexpr int D   = 64;
constexpr int TM  = 128;
constexpr int TN  = 64;
constexpr int DC  = 32;    // two d-chunks
constexpr int STA = 132;   // As stride (128 + 4 pad)
constexpr int STB = 68;    // Bs stride (64 + 4 pad)

__global__ __launch_bounds__(256, 3)
void l1dist_kernel(const float* __restrict__ x1, const float* __restrict__ x2,
                   float* __restrict__ out, int N2) {
    __shared__ __align__(16) float As[DC * STA];  // As[d][row] = x1[i0+row][dc+d]
    __shared__ __align__(16) float Bs[DC * STB];  // Bs[d][row] = x2[j0+row][dc+d]
    __shared__ float rsAs[TM];
    __shared__ float rsBs[TN];

    const int i0  = blockIdx.y * TM;
    const int j0  = blockIdx.x * TN;
    const int tid = (int)threadIdx.x;
    const int ty  = tid >> 4;     // 0..15: rows ty*4+{0..3}, 64+ty*4+{0..3}
    const int tx  = tid & 15;     // 0..15: cols tx*4+{0..3}
    const int w   = tid >> 5;     // warp 0..7
    const int l   = tid & 31;     // lane

    float acc[8][4];
#pragma unroll
    for (int m = 0; m < 8; m++)
#pragma unroll
        for (int n = 0; n < 4; n++) acc[m][n] = 0.0f;

    float rs = 0.0f;

    for (int dc = 0; dc < D; dc += DC) {
        // ---- stage A: LDG.128 + 4x STS.32 (bank stride 1, conflict-free) ----
        {
            int rowA = (w & 3) * 32 + l;
            const float* pA = x1 + (size_t)(i0 + rowA) * D + dc + (w >> 2) * 4;
#pragma unroll
            for (int it = 0; it < 4; it++) {
                float4 v = *(const float4*)(pA + it * 8);
                int d0 = (w >> 2) * 4 + it * 8;
                As[(d0 + 0) * STA + rowA] = v.x;
                As[(d0 + 1) * STA + rowA] = v.y;
                As[(d0 + 2) * STA + rowA] = v.z;
                As[(d0 + 3) * STA + rowA] = v.w;
            }
        }
        // ---- stage B ----
        {
            int rowB = (w & 1) * 32 + l;
            const float* pB = x2 + (size_t)(j0 + rowB) * D + dc + (w >> 1) * 8;
#pragma unroll
            for (int it = 0; it < 2; it++) {
                float4 v = *(const float4*)(pB + it * 4);
                int d0 = (w >> 1) * 8 + it * 4;
                Bs[(d0 + 0) * STB + rowB] = v.x;
                Bs[(d0 + 1) * STB + rowB] = v.y;
                Bs[(d0 + 2) * STB + rowB] = v.z;
                Bs[(d0 + 3) * STB + rowB] = v.w;
            }
        }
        __syncthreads();

        // ---- partial rowsums ----
        if (tid < TM) {
            const float* col = &As[tid];
#pragma unroll
            for (int d = 0; d < DC; d++) rs += col[d * STA];
        } else if (tid < TM + TN) {
            const float* col = &Bs[tid - TM];
#pragma unroll
            for (int d = 0; d < DC; d++) rs += col[d * STB];
        }

        // ---- compute: two 16-FMNMX / 16-FADD phases per d ----
        const float* asb = As + ty * 4;
        const float* bsb = Bs + tx * 4;
#pragma unroll 4
        for (int d = 0; d < DC; d++) {
            float4 a0 = *(const float4*)(asb + d * STA);
            float4 a1 = *(const float4*)(asb + d * STA + 64);
            float4 bv = *(const float4*)(bsb + d * STB);

            float t[16];
            // phase 1: rows 0..3 (a0)
            {
                float ra[4] = {a0.x, a0.y, a0.z, a0.w};
#pragma unroll
                for (int m = 0; m < 4; m++) {
                    t[m * 4 + 0] = fminf(ra[m], bv.x);
                    t[m * 4 + 1] = fminf(ra[m], bv.y);
                    t[m * 4 + 2] = fminf(ra[m], bv.z);
                    t[m * 4 + 3] = fminf(ra[m], bv.w);
                }
#pragma unroll
                for (int m = 0; m < 4; m++) {
                    acc[m][0] += t[m * 4 + 0];
                    acc[m][1] += t[m * 4 + 1];
                    acc[m][2] += t[m * 4 + 2];
                    acc[m][3] += t[m * 4 + 3];
                }
            }
            // phase 2: rows 4..7 (a1)
            {
                float ra[4] = {a1.x, a1.y, a1.z, a1.w};
#pragma unroll
                for (int m = 0; m < 4; m++) {
                    t[m * 4 + 0] = fminf(ra[m], bv.x);
                    t[m * 4 + 1] = fminf(ra[m], bv.y);
                    t[m * 4 + 2] = fminf(ra[m], bv.z);
                    t[m * 4 + 3] = fminf(ra[m], bv.w);
                }
#pragma unroll
                for (int m = 0; m < 4; m++) {
                    acc[4 + m][0] += t[m * 4 + 0];
                    acc[4 + m][1] += t[m * 4 + 1];
                    acc[4 + m][2] += t[m * 4 + 2];
                    acc[4 + m][3] += t[m * 4 + 3];
                }
            }
        }
        __syncthreads();
    }

    // ---- publish rowsums ----
    if (tid < TM)            rsAs[tid] = rs;
    else if (tid < TM + TN)  rsBs[tid - TM] = rs;
    __syncthreads();

    float rsb[4] = {rsBs[tx * 4 + 0], rsBs[tx * 4 + 1],
                    rsBs[tx * 4 + 2], rsBs[tx * 4 + 3]};

    // ---- epilogue: out = max(rsA + rsB - 2*acc, 0) ----
#pragma unroll
    for (int m = 0; m < 8; m++) {
        int rloc = (m < 4) ? (ty * 4 + m) : (64 + ty * 4 + (m - 4));
        float rsa = rsAs[rloc];
        float* orow = out + (size_t)(i0 + rloc) * N2 + j0 + tx * 4;
        *(float4*)orow = make_float4(
            fmaxf(fmaf(-2.f, acc[m][0], rsa + rsb[0]), 0.f),
            fmaxf(fmaf(-2.f, acc[m][1], rsa + rsb[1]), 0.f),
            fmaxf(fmaf(-2.f, acc[m][2], rsa + rsb[2]), 0.f),
            fmaxf(fmaf(-2.f, acc[m][3], rsa + rsb[3]), 0.f));
    }
}

extern "C" void kernel_launch(void* const* d_in, const int* in_sizes, int n_in,
                              void* d_out, int out_size) {
    const float* x1 = (const float*)d_in[0];
    const float* x2 = (const float*)d_in[1];
    float* out = (float*)d_out;

    int N1 = in_sizes[0] / D;   // 2048
    int N2 = in_sizes[1] / D;   // 2048

    dim3 grid(N2 / TN, N1 / TM);   // 32 x 16 = 512 blocks
    l1dist_kernel<<<grid, 256>>>(x1, x2, out, N2);
}

// round 15
// speedup vs baseline: 1.0663x; 1.0663x over previous
#include <cuda_runtime.h>

// L1Distance, d-vectorized row-major formulation (no transpose):
//   min accs (21/32):   acc += min(a,b);  out = max(rsA+rsB-2*acc, 0)
//   direct accs (11/32): acc += |a-b|;    out = max(acc, 0)
// selector (4m+n)%3==0 -> direct; p_min ~ 2/3 balances fma(rt1)/alu(rt2) pipes.
// Each LDS.128 covers 4 consecutive d's. A-loads are warp-broadcast; B-loads
// conflict-free via col mapping {tx+16n} (row stride 9 x16B units, odd mod 8).
// Staging is a coalesced identity copy (STS.128, conflict-free).

constexpr int D  = 64;
constexpr int TM = 128;
constexpr int TN = 64;
constexpr int DC = 32;            // two d-chunks
constexpr int SW = DC + 4;        // row stride in floats (36 = 9 x 16B units)

__global__ __launch_bounds__(256, 3)
void l1dist_kernel(const float* __restrict__ x1, const float* __restrict__ x2,
                   float* __restrict__ out, int N2) {
    __shared__ __align__(16) float As[TM * SW];   // As[row][d] row-major
    __shared__ __align__(16) float Bs[TN * SW];
    __shared__ float rsAs[TM];
    __shared__ float rsBs[TN];

    const int i0  = blockIdx.y * TM;
    const int j0  = blockIdx.x * TN;
    const int tid = (int)threadIdx.x;
    const int ty  = tid >> 4;    // 0..15 -> rows ty*8 .. ty*8+7
    const int tx  = tid & 15;    // 0..15 -> cols tx, tx+16, tx+32, tx+48

    float acc[8][4];
#pragma unroll
    for (int m = 0; m < 8; m++)
#pragma unroll
        for (int n = 0; n < 4; n++) acc[m][n] = 0.0f;

    float rs = 0.0f;

    for (int dc = 0; dc < D; dc += DC) {
        // ---- stage A: identity copy, 128 rows x 8 float4 (coalesced, CF) ----
#pragma unroll
        for (int k = 0; k < 4; k++) {
            int idx = tid + k * 256;          // 0..1023
            int row = idx >> 3;               // 0..127
            int q   = idx & 7;                // float4 index within row
            float4 v = *(const float4*)(x1 + (size_t)(i0 + row) * D + dc + q * 4);
            *(float4*)(&As[row * SW + q * 4]) = v;
        }
        // ---- stage B: 64 rows x 8 float4 ----
#pragma unroll
        for (int k = 0; k < 2; k++) {
            int idx = tid + k * 256;          // 0..511
            int row = idx >> 3;               // 0..63
            int q   = idx & 7;
            float4 v = *(const float4*)(x2 + (size_t)(j0 + row) * D + dc + q * 4);
            *(float4*)(&Bs[row * SW + q * 4]) = v;
        }
        __syncthreads();

        // ---- partial rowsums (float4 passes, stride 9 units -> CF) ----
        if (tid < TM) {
            const float* r = &As[tid * SW];
#pragma unroll
            for (int q = 0; q < 8; q++) {
                float4 v = *(const float4*)(r + q * 4);
                rs += (v.x + v.y) + (v.z + v.w);
            }
        } else if (tid < TM + TN) {
            const float* r = &Bs[(tid - TM) * SW];
#pragma unroll
            for (int q = 0; q < 8; q++) {
                float4 v = *(const float4*)(r + q * 4);
                rs += (v.x + v.y) + (v.z + v.w);
            }
        }

        // ---- compute: 8 steps of 4 d's each ----
#pragma unroll 4
        for (int s = 0; s < DC / 4; s++) {
            float4 b0 = *(const float4*)(&Bs[(tx)      * SW + s * 4]);
            float4 b1 = *(const float4*)(&Bs[(tx + 16) * SW + s * 4]);
            float4 b2 = *(const float4*)(&Bs[(tx + 32) * SW + s * 4]);
            float4 b3 = *(const float4*)(&Bs[(tx + 48) * SW + s * 4]);
#pragma unroll
            for (int m = 0; m < 8; m++) {
                float4 a = *(const float4*)(&As[(ty * 8 + m) * SW + s * 4]);
#define PAIR_UPD(n, bv)                                            \
                if (((4 * m + n) % 3) == 0) {                      \
                    acc[m][n] += fabsf(a.x - bv.x);                \
                    acc[m][n] += fabsf(a.y - bv.y);                \
                    acc[m][n] += fabsf(a.z - bv.z);                \
                    acc[m][n] += fabsf(a.w - bv.w);                \
                } else {                                           \
                    acc[m][n] += fminf(a.x, bv.x);                 \
                    acc[m][n] += fminf(a.y, bv.y);                 \
                    acc[m][n] += fminf(a.z, bv.z);                 \
                    acc[m][n] += fminf(a.w, bv.w);                 \
                }
                PAIR_UPD(0, b0)
                PAIR_UPD(1, b1)
                PAIR_UPD(2, b2)
                PAIR_UPD(3, b3)
#undef PAIR_UPD
            }
        }
        __syncthreads();
    }

    // ---- publish rowsums ----
    if (tid < TM)            rsAs[tid] = rs;
    else if (tid < TM + TN)  rsBs[tid - TM] = rs;
    __syncthreads();

    float rsb[4] = {rsBs[tx], rsBs[tx + 16], rsBs[tx + 32], rsBs[tx + 48]};

    // ---- epilogue ----
#pragma unroll
    for (int m = 0; m < 8; m++) {
        int rloc = ty * 8 + m;
        float rsa = rsAs[rloc];
        float* orow = out + (size_t)(i0 + rloc) * N2 + j0 + tx;
#pragma unroll
        for (int n = 0; n < 4; n++) {
            float v;
            if (((4 * m + n) % 3) == 0) v = fmaxf(acc[m][n], 0.f);
            else v = fmaxf(fmaf(-2.f, acc[m][n], rsa + rsb[n]), 0.f);
            orow[n * 16] = v;
        }
    }
}

extern "C" void kernel_launch(void* const* d_in, const int* in_sizes, int n_in,
                              void* d_out, int out_size) {
    const float* x1 = (const float*)d_in[0];
    const float* x2 = (const float*)d_in[1];
    float* out = (float*)d_out;

    int N1 = in_sizes[0] / D;   // 2048
    int N2 = in_sizes[1] / D;   // 2048

    dim3 grid(N2 / TN, N1 / TM);   // 32 x 16 = 512 blocks
    l1dist_kernel<<<grid, 256>>>(x1, x2, out, N2);
}

// round 16
// speedup vs baseline: 1.2173x; 1.1416x over previous
#include <cuda_runtime.h>

// L1Distance, FFMA-imm (rt1) formulation on the champion R1 geometry:
//   t   = fmaf(a, 2.0f, -b2)      (b2 = 2b staged)  -> FFMA R,R,2.0,-R  rt1
//   acc = fmaf(|t|, 2.0f, acc)                      -> FFMA R,|R|,2.0,R rt1
//   out = max(0.25f * acc, 0)     (exact /4; mean-adjustment cancels)
// FADD is rt2 on the fma pipe; imm-multiplier FFMA is rt1 -> pipe busy halves
// from 56.6K to 28.3K cyc/SMSP. Multiplier 2.0 prevents FADD refolding.

constexpr int D      = 64;
constexpr int TILE   = 128;   // output tile per block (128x128)
constexpr int DCHUNK = 32;    // d staged in two chunks
constexpr int STRIDE = 132;   // padded smem row stride (floats)

__global__ __launch_bounds__(256, 2)
void l1dist_kernel(const float* __restrict__ x1, const float* __restrict__ x2,
                   float* __restrict__ out, int N2) {
    __shared__ __align__(16) float As[DCHUNK * STRIDE];  // As[d][row] = x1[i0+row][dc+d]
    __shared__ __align__(16) float Bs[DCHUNK * STRIDE];  // Bs[d][row] = 2*x2[j0+row][dc+d]

    const int i0  = blockIdx.y * TILE;
    const int j0  = blockIdx.x * TILE;
    const int tid = (int)threadIdx.x;
    const int ty  = tid >> 4;   // 0..15
    const int tx  = tid & 15;   // 0..15

    float acc[8][8];
#pragma unroll
    for (int m = 0; m < 8; m++)
#pragma unroll
        for (int n = 0; n < 8; n++) acc[m][n] = 0.0f;

    for (int dc = 0; dc < D; dc += DCHUNK) {
        // ---- stage chunk: 128 rows x 32 d, transposed; B scaled by 2 ----
#pragma unroll
        for (int k = 0; k < 4; k++) {
            int idx = tid + k * 256;        // 0..1023
            int row = idx >> 3;             // 0..127
            int d4  = (idx & 7) << 2;       // 0,4,...,28
            float4 a = *(const float4*)(x1 + (size_t)(i0 + row) * D + dc + d4);
            As[(d4 + 0) * STRIDE + row] = a.x;
            As[(d4 + 1) * STRIDE + row] = a.y;
            As[(d4 + 2) * STRIDE + row] = a.z;
            As[(d4 + 3) * STRIDE + row] = a.w;
            float4 b = *(const float4*)(x2 + (size_t)(j0 + row) * D + dc + d4);
            Bs[(d4 + 0) * STRIDE + row] = 2.0f * b.x;
            Bs[(d4 + 1) * STRIDE + row] = 2.0f * b.y;
            Bs[(d4 + 2) * STRIDE + row] = 2.0f * b.z;
            Bs[(d4 + 3) * STRIDE + row] = 2.0f * b.w;
        }
        __syncthreads();

        // ---- compute: per pair, 2x FFMA-imm (rt1) ----
#pragma unroll 4
        for (int d = 0; d < DCHUNK; d++) {
            const float* as = &As[d * STRIDE];
            const float* bs = &Bs[d * STRIDE];
            float4 a0 = *(const float4*)(as + ty * 4);
            float4 a1 = *(const float4*)(as + ty * 4 + 64);
            float4 b0 = *(const float4*)(bs + tx * 4);
            float4 b1 = *(const float4*)(bs + tx * 4 + 64);
            float ra[8] = {a0.x, a0.y, a0.z, a0.w, a1.x, a1.y, a1.z, a1.w};
            float rb[8] = {b0.x, b0.y, b0.z, b0.w, b1.x, b1.y, b1.z, b1.w};
#pragma unroll
            for (int m = 0; m < 8; m++)
#pragma unroll
                for (int n = 0; n < 8; n++) {
                    float t = fmaf(ra[m], 2.0f, -rb[n]);     // 2a - 2b
                    acc[m][n] = fmaf(fabsf(t), 2.0f, acc[m][n]);  // += 4|a-b|
                }
        }
        __syncthreads();
    }

    // ---- store: out = max(acc/4, 0), float4 per 4 adjacent columns ----
#pragma unroll
    for (int m = 0; m < 8; m++) {
        int r = i0 + ty * 4 + (m & 3) + ((m >> 2) << 6);
        float* orow = out + (size_t)r * N2 + j0 + tx * 4;
#pragma unroll
        for (int n4 = 0; n4 < 2; n4++) {
            float4 v = make_float4(
                fmaxf(0.25f * acc[m][n4 * 4 + 0], 0.f),
                fmaxf(0.25f * acc[m][n4 * 4 + 1], 0.f),
                fmaxf(0.25f * acc[m][n4 * 4 + 2], 0.f),
                fmaxf(0.25f * acc[m][n4 * 4 + 3], 0.f));
            *(float4*)(orow + (n4 << 6)) = v;
        }
    }
}

extern "C" void kernel_launch(void* const* d_in, const int* in_sizes, int n_in,
                              void* d_out, int out_size) {
    const float* x1 = (const float*)d_in[0];
    const float* x2 = (const float*)d_in[1];
    float* out = (float*)d_out;

    int N1 = in_sizes[0] / D;   // 2048
    int N2 = in_sizes[1] / D;   // 2048

    dim3 grid(N2 / TILE, N1 / TILE);   // 16 x 16 = 256 blocks
    l1dist_kernel<<<grid, 256>>>(x1, x2, out, N2);
}